// round 15
// baseline (speedup 1.0000x reference)
#include <cuda_runtime.h>
#include <math.h>

#define Dn   128
#define SQn  16
#define SKn  4096
#define BHn  64
#define TILE 128
#define NTHREADS 256
#define NWARPS   8
#define NBLOCKS  (BHn * (SKn / TILE))   /* 2048 */

typedef unsigned long long u64;

/* device scratch (no allocation allowed) */
__device__ float g_Rt[Dn*Dn];     /* Rt[d][j] = R[j][d] */
__device__ float g_St[Dn*Dn];     /* St[d][m] = S[m][d] */
__device__ float g_qR[BHn*SQn*Dn];
__device__ float g_qS[BHn*SQn*Dn];

/* ---- prep 1: transposes (coalesced stores) ---- */
__global__ void prep1(const float* __restrict__ rot, const float* __restrict__ S)
{
    int j = blockIdx.x, t = threadIdx.x;       /* 128 x 128 */
    g_Rt[t*Dn + j] = rot[j*Dn + t];
    g_St[t*Dn + j] = S[j*Dn + t];
}

/* ---- prep 2 (coalesced): qR/qS, continuous outputs ---- */
__global__ void prep_q(const float* __restrict__ query)
{
    __shared__ float sq[Dn];
    const int bq = blockIdx.x;                  /* 0..1023 = bh*16 + q */
    const int j  = threadIdx.x;                 /* 128 threads */
    if (j < Dn) sq[j] = query[(size_t)bq*Dn + j];
    __syncthreads();

    float a0 = 0.f, a1 = 0.f, a2 = 0.f, a3 = 0.f;
    float b0 = 0.f, b1 = 0.f, b2 = 0.f, b3 = 0.f;
#pragma unroll 8
    for (int d = 0; d < Dn; d += 4) {
        float q0 = sq[d+0], q1 = sq[d+1], q2 = sq[d+2], q3 = sq[d+3];
        a0 = __fmaf_rn(q0, g_Rt[(d+0)*Dn + j], a0);
        a1 = __fmaf_rn(q1, g_Rt[(d+1)*Dn + j], a1);
        a2 = __fmaf_rn(q2, g_Rt[(d+2)*Dn + j], a2);
        a3 = __fmaf_rn(q3, g_Rt[(d+3)*Dn + j], a3);
        b0 = __fmaf_rn(q0, g_St[(d+0)*Dn + j], b0);
        b1 = __fmaf_rn(q1, g_St[(d+1)*Dn + j], b1);
        b2 = __fmaf_rn(q2, g_St[(d+2)*Dn + j], b2);
        b3 = __fmaf_rn(q3, g_St[(d+3)*Dn + j], b3);
    }
    g_qR[(size_t)bq*Dn + j] = (a0 + a1) + (a2 + a3);
    g_qS[(size_t)bq*Dn + j] = (b0 + b1) + (b2 + b3);
}

__device__ __forceinline__ float wsum(float v)
{
#pragma unroll
    for (int o = 16; o > 0; o >>= 1) v += __shfl_xor_sync(0xffffffffu, v, o);
    return v;
}

/* ---- packed f32x2 helpers (two independent IEEE fp32 ops each) ---- */
__device__ __forceinline__ u64 pk2(float lo, float hi)
{ u64 r; asm("mov.b64 %0,{%1,%2};" : "=l"(r) : "f"(lo), "f"(hi)); return r; }
__device__ __forceinline__ u64 dup2(float x)
{ u64 r; asm("mov.b64 %0,{%1,%1};" : "=l"(r) : "f"(x)); return r; }
__device__ __forceinline__ void fma2(u64& acc, u64 a, u64 b)
{ asm("fma.rn.f32x2 %0,%1,%2,%0;" : "+l"(acc) : "l"(a), "l"(b)); }
__device__ __forceinline__ float2 unpk(u64 v)
{ float2 f; asm("mov.b64 {%0,%1},%2;" : "=f"(f.x), "=f"(f.y) : "l"(v)); return f; }

/* ---- main fused kernel: one block = 128 keys of one (b,h), 8 warps,
   16 keys per warp (2 halves of 8 sharing each matrix load) ---- */
__global__ void __launch_bounds__(NTHREADS, 1)
turbo_main(const float* __restrict__ keys, const float* __restrict__ rot,
           const float* __restrict__ levels, float* __restrict__ out)
{
    __shared__ float  sM[Dn*Dn];        /* 64K: Rt -> St (phase 2 uses __ldg rot) */
    __shared__ float  sK[TILE*Dn];      /* 64K: raw keys -> r_hat */
    __shared__ float  sQR[SQn*Dn];      /*  8K */
    __shared__ float  sQS[SQn*Dn];      /*  8K */
    __shared__ float  sTab[256*4];      /*  4K: byte -> 4 level values */
    __shared__ float  sNorm[TILE];
    __shared__ float  sRn[TILE];
    __shared__ unsigned sSign[TILE*4];  /*  2K */
    __shared__ unsigned char sCodeB[TILE*32]; /* 4K: 2-bit yhat codes */

    const int tid = threadIdx.x, w = tid >> 5, lane = tid & 31;
    const int bh  = blockIdx.x >> 5;            /* 32 tiles per bh */
    const int k0  = (blockIdx.x & 31) * TILE;
    const float* keys_blk = keys + ((size_t)bh*SKn + k0)*Dn;

    const float L0 = __ldg(levels+0), L1 = __ldg(levels+1),
                L2 = __ldg(levels+2), L3 = __ldg(levels+3);
    const float bb0 = 0.5f*(L0+L1), bb1 = 0.5f*(L1+L2), bb2 = 0.5f*(L2+L3);

    /* cooperative loads */
    {
        const float4* g = (const float4*)keys_blk;
        float4* s = (float4*)sK;
#pragma unroll
        for (int i = tid; i < TILE*Dn/4; i += NTHREADS) s[i] = g[i];
    }
    {
        const float4* g = (const float4*)g_Rt; float4* s = (float4*)sM;
#pragma unroll
        for (int i = tid; i < Dn*Dn/4; i += NTHREADS) s[i] = g[i];
    }
    {
        const float4* g = (const float4*)(g_qR + bh*SQn*Dn); float4* s = (float4*)sQR;
#pragma unroll
        for (int i = tid; i < SQn*Dn/4; i += NTHREADS) s[i] = g[i];
        g = (const float4*)(g_qS + bh*SQn*Dn); s = (float4*)sQS;
#pragma unroll
        for (int i = tid; i < SQn*Dn/4; i += NTHREADS) s[i] = g[i];
    }
    /* byte -> float4 level decode table (exact level values) */
    {
        unsigned b = tid;
        float v[4];
#pragma unroll
        for (int c = 0; c < 4; ++c) {
            unsigned cc = (b >> (2*c)) & 3u;
            float lo = (cc & 1u) ? L1 : L0;
            float hi = (cc & 1u) ? L3 : L2;
            v[c] = (cc & 2u) ? hi : lo;
        }
        ((float4*)sTab)[b] = make_float4(v[0],v[1],v[2],v[3]);
    }
    __syncthreads();

    const int kb = w*16;

    /* norms (fp32, deterministic order); each warp owns 16 keys */
    float nk[16];
#pragma unroll
    for (int i = 0; i < 16; ++i) {
        int key = kb + i;
        float4 v = ((const float4*)(sK + key*Dn))[lane];
        float ss = __fmul_rn(v.x, v.x);
        ss = __fmaf_rn(v.y, v.y, ss);
        ss = __fmaf_rn(v.z, v.z, ss);
        ss = __fmaf_rn(v.w, v.w, ss);
        ss = wsum(ss);
        float n = fmaxf(__fsqrt_rn(ss), 1e-8f);
        nk[i] = n;
        if (lane == 0) sNorm[key] = n;
    }
    __syncwarp();

    /* ===== phase 1: y = fl(k/n) @ R^T (seq FMA over d, div fused); codes ===== */
    {
        u64 axy[16], azw[16];
#pragma unroll
        for (int i = 0; i < 16; ++i) { axy[i] = 0ULL; azw[i] = 0ULL; }
        for (int db = 0; db < Dn; db += 4) {
            u64 rx[4], rz[4];
#pragma unroll
            for (int dd = 0; dd < 4; ++dd) {
                float4 r = ((const float4*)sM)[(db+dd)*32 + lane];
                rx[dd] = pk2(r.x, r.y); rz[dd] = pk2(r.z, r.w);
            }
#pragma unroll
            for (int h = 0; h < 2; ++h) {
                float xs[8][4];
#pragma unroll
                for (int i = 0; i < 8; ++i) {
                    float n = nk[h*8 + i];
                    float4 x = *(const float4*)(sK + (kb + h*8 + i)*Dn + db);
                    xs[i][0] = __fdiv_rn(x.x, n);   /* k_hat = fl(k/n), IEEE */
                    xs[i][1] = __fdiv_rn(x.y, n);
                    xs[i][2] = __fdiv_rn(x.z, n);
                    xs[i][3] = __fdiv_rn(x.w, n);
                }
#pragma unroll
                for (int dd = 0; dd < 4; ++dd)
#pragma unroll
                    for (int i = 0; i < 8; ++i) {
                        u64 xx = dup2(xs[i][dd]);
                        fma2(axy[h*8+i], xx, rx[dd]);
                        fma2(azw[h*8+i], xx, rz[dd]);
                    }
            }
        }
#pragma unroll
        for (int i = 0; i < 16; ++i) {
            float2 lo = unpk(axy[i]), hi = unpk(azw[i]);
            unsigned c0, c1, c2, c3;
            { float y = lo.x; c0 = (unsigned)(y > bb0) + (unsigned)(y > bb1) + (unsigned)(y > bb2); }
            { float y = lo.y; c1 = (unsigned)(y > bb0) + (unsigned)(y > bb1) + (unsigned)(y > bb2); }
            { float y = hi.x; c2 = (unsigned)(y > bb0) + (unsigned)(y > bb1) + (unsigned)(y > bb2); }
            { float y = hi.y; c3 = (unsigned)(y > bb0) + (unsigned)(y > bb1) + (unsigned)(y > bb2); }
            sCodeB[(kb+i)*32 + lane] = (unsigned char)(c0 | (c1<<2) | (c2<<4) | (c3<<6));
        }
    }
    __syncthreads();

    /* ===== phase 2: keys_mse = fl(fl(yhat@R)*n); residual; r_hat
       (matrix rows streamed from global rot via coalesced L1 loads) ===== */
    {
        u64 axy[16], azw[16];
#pragma unroll
        for (int i = 0; i < 16; ++i) { axy[i] = 0ULL; azw[i] = 0ULL; }
        for (int g = 0; g < 32; ++g) {          /* j = 4g..4g+3 */
            u64 rx[4], rz[4];
#pragma unroll
            for (int dd = 0; dd < 4; ++dd) {
                float4 r = __ldg(((const float4*)(rot + (size_t)(4*g+dd)*Dn)) + lane);
                rx[dd] = pk2(r.x, r.y); rz[dd] = pk2(r.z, r.w);
            }
#pragma unroll
            for (int h = 0; h < 2; ++h) {
                float xs[8][4];
#pragma unroll
                for (int i = 0; i < 8; ++i) {
                    float4 x = ((const float4*)sTab)[sCodeB[(kb + h*8 + i)*32 + g]];
                    xs[i][0]=x.x; xs[i][1]=x.y; xs[i][2]=x.z; xs[i][3]=x.w;
                }
#pragma unroll
                for (int dd = 0; dd < 4; ++dd)
#pragma unroll
                    for (int i = 0; i < 8; ++i) {
                        u64 xx = dup2(xs[i][dd]);
                        fma2(axy[h*8+i], xx, rx[dd]);
                        fma2(azw[h*8+i], xx, rz[dd]);
                    }
            }
        }
#pragma unroll
        for (int i = 0; i < 16; ++i) {
            int key = kb + i;
            float n = nk[i];
            float2 lo = unpk(axy[i]), hi = unpk(azw[i]);
            float4 kg = ((const float4*)(sK + key*Dn))[lane];   /* raw keys, in smem */
            float4 r;
            r.x = __fadd_rn(kg.x, -__fmul_rn(lo.x, n));
            r.y = __fadd_rn(kg.y, -__fmul_rn(lo.y, n));
            r.z = __fadd_rn(kg.z, -__fmul_rn(hi.x, n));
            r.w = __fadd_rn(kg.w, -__fmul_rn(hi.y, n));
            float ss = __fmul_rn(r.x, r.x);
            ss = __fmaf_rn(r.y, r.y, ss);
            ss = __fmaf_rn(r.z, r.z, ss);
            ss = __fmaf_rn(r.w, r.w, ss);
            ss = wsum(ss);
            float rn = fmaxf(__fsqrt_rn(ss), 1e-10f);
            if (lane == 0) sRn[key] = rn;
            float4 rh;
            rh.x = __fdiv_rn(r.x, rn);
            rh.y = __fdiv_rn(r.y, rn);
            rh.z = __fdiv_rn(r.z, rn);
            rh.w = __fdiv_rn(r.w, rn);
            ((float4*)(sK + key*Dn))[lane] = rh;   /* keys -> r_hat */
        }
    }
    __syncthreads();

    /* reload matrix slot: St[d][m] */
    {
        const float4* g = (const float4*)g_St; float4* s = (float4*)sM;
#pragma unroll
        for (int i = tid; i < Dn*Dn/4; i += NTHREADS) s[i] = g[i];
    }
    __syncthreads();

    /* ===== phase 3: proj = r_hat @ S^T (seq FMA over d); signs ===== */
    {
        u64 axy[16], azw[16];
#pragma unroll
        for (int i = 0; i < 16; ++i) { axy[i] = 0ULL; azw[i] = 0ULL; }
        for (int db = 0; db < Dn; db += 4) {
            u64 rx[4], rz[4];
#pragma unroll
            for (int dd = 0; dd < 4; ++dd) {
                float4 r = ((const float4*)sM)[(db+dd)*32 + lane];
                rx[dd] = pk2(r.x, r.y); rz[dd] = pk2(r.z, r.w);
            }
#pragma unroll
            for (int h = 0; h < 2; ++h) {
                float xs[8][4];
#pragma unroll
                for (int i = 0; i < 8; ++i) {
                    float4 x = *(const float4*)(sK + (kb + h*8 + i)*Dn + db);
                    xs[i][0]=x.x; xs[i][1]=x.y; xs[i][2]=x.z; xs[i][3]=x.w;
                }
#pragma unroll
                for (int dd = 0; dd < 4; ++dd)
#pragma unroll
                    for (int i = 0; i < 8; ++i) {
                        u64 xx = dup2(xs[i][dd]);
                        fma2(axy[h*8+i], xx, rx[dd]);
                        fma2(azw[h*8+i], xx, rz[dd]);
                    }
            }
        }
#pragma unroll
        for (int i = 0; i < 16; ++i) {
            float2 lo = unpk(axy[i]), hi = unpk(azw[i]);
            unsigned b0 = __ballot_sync(0xffffffffu, lo.x >= 0.f);
            unsigned b1 = __ballot_sync(0xffffffffu, lo.y >= 0.f);
            unsigned b2 = __ballot_sync(0xffffffffu, hi.x >= 0.f);
            unsigned b3 = __ballot_sync(0xffffffffu, hi.y >= 0.f);
            if (lane == 0) {
                unsigned* sp = sSign + (size_t)(kb+i)*4;
                sp[0]=b0; sp[1]=b1; sp[2]=b2; sp[3]=b3;
            }
        }
    }
    __syncthreads();

    /* ===== epilogue (shfl-free, merged e/s loop): warp -> 2 q rows, lane -> 4 keys ===== */
    {
        const float cq = 0.0097915167f;   /* sqrt(pi/2)/128 */
        const int q0 = 2*w, q1 = 2*w + 1;
        const float* qr0 = sQR + q0*Dn;
        const float* qr1 = sQR + q1*Dn;
        const float* qs0 = sQS + q0*Dn;
        const float* qs1 = sQS + q1*Dn;
        float* og = out + ((size_t)bh*SQn)*SKn + k0;

#pragma unroll
        for (int kc = 0; kc < 4; ++kc) {        /* key columns lane + 32*kc */
            const int key = lane + 32*kc;
            const unsigned char* cK = sCodeB + key*32;
            unsigned w0 = sSign[key*4+0], w1 = sSign[key*4+1],
                     w2 = sSign[key*4+2], w3 = sSign[key*4+3];
            float e0 = 0.f, e1 = 0.f, s0 = 0.f, s1 = 0.f;
#pragma unroll 4
            for (int g = 0; g < 32; ++g) {
                float4 a0 = ((const float4*)qr0)[g];
                float4 a1 = ((const float4*)qr1)[g];
                float4 yv = ((const float4*)sTab)[cK[g]];
                float4 b0 = ((const float4*)qs0)[g];
                float4 b1 = ((const float4*)qs1)[g];
                e0 = __fmaf_rn(a0.x, yv.x, e0); e0 = __fmaf_rn(a0.y, yv.y, e0);
                e0 = __fmaf_rn(a0.z, yv.z, e0); e0 = __fmaf_rn(a0.w, yv.w, e0);
                e1 = __fmaf_rn(a1.x, yv.x, e1); e1 = __fmaf_rn(a1.y, yv.y, e1);
                e1 = __fmaf_rn(a1.z, yv.z, e1); e1 = __fmaf_rn(a1.w, yv.w, e1);
                float f0 = ((w0 >> g) & 1u) ? 1.f : -1.f;
                float f1 = ((w1 >> g) & 1u) ? 1.f : -1.f;
                float f2 = ((w2 >> g) & 1u) ? 1.f : -1.f;
                float f3 = ((w3 >> g) & 1u) ? 1.f : -1.f;
                s0 = __fmaf_rn(f0, b0.x, s0); s0 = __fmaf_rn(f1, b0.y, s0);
                s0 = __fmaf_rn(f2, b0.z, s0); s0 = __fmaf_rn(f3, b0.w, s0);
                s1 = __fmaf_rn(f0, b1.x, s1); s1 = __fmaf_rn(f1, b1.y, s1);
                s1 = __fmaf_rn(f2, b1.z, s1); s1 = __fmaf_rn(f3, b1.w, s1);
            }
            float n = sNorm[key], g2 = cq * sRn[key];
            og[(size_t)q0*SKn + key] = n*e0 + g2*s0;
            og[(size_t)q1*SKn + key] = n*e1 + g2*s1;
        }
    }
}

extern "C" void kernel_launch(void* const* d_in, const int* in_sizes, int n_in,
                              void* d_out, int out_size)
{
    const float* query  = (const float*)d_in[0];
    const float* keys   = (const float*)d_in[1];
    const float* rot    = (const float*)d_in[2];
    const float* S      = (const float*)d_in[3];
    const float* levels = (const float*)d_in[4];
    float* out = (float*)d_out;

    prep1<<<Dn, Dn>>>(rot, S);
    prep_q<<<BHn*SQn, Dn>>>(query);
    turbo_main<<<NBLOCKS, NTHREADS>>>(keys, rot, levels, out);
}

// round 16
// speedup vs baseline: 1.8936x; 1.8936x over previous
#include <cuda_runtime.h>
#include <math.h>

#define Dn   128
#define SQn  16
#define SKn  4096
#define BHn  64
#define TILE 128
#define NTHREADS 256
#define NWARPS   8
#define NBLOCKS  (BHn * (SKn / TILE))   /* 2048 */

typedef unsigned long long u64;

/* device scratch (no allocation allowed) */
__device__ float g_Rt[Dn*Dn];     /* Rt[d][j] = R[j][d] */
__device__ float g_St[Dn*Dn];     /* St[d][m] = S[m][d] */
__device__ float g_qR[BHn*SQn*Dn];
__device__ float g_qS[BHn*SQn*Dn];

/* ---- prep 1: transposes (coalesced stores) ---- */
__global__ void prep1(const float* __restrict__ rot, const float* __restrict__ S)
{
    int j = blockIdx.x, t = threadIdx.x;       /* 128 x 128 */
    g_Rt[t*Dn + j] = rot[j*Dn + t];
    g_St[t*Dn + j] = S[j*Dn + t];
}

/* ---- prep 2 (coalesced): qR/qS, continuous outputs ---- */
__global__ void prep_q(const float* __restrict__ query)
{
    __shared__ float sq[Dn];
    const int bq = blockIdx.x;                  /* 0..1023 = bh*16 + q */
    const int j  = threadIdx.x;                 /* 128 threads */
    if (j < Dn) sq[j] = query[(size_t)bq*Dn + j];
    __syncthreads();

    float a0 = 0.f, a1 = 0.f, a2 = 0.f, a3 = 0.f;
    float b0 = 0.f, b1 = 0.f, b2 = 0.f, b3 = 0.f;
#pragma unroll 8
    for (int d = 0; d < Dn; d += 4) {
        float q0 = sq[d+0], q1 = sq[d+1], q2 = sq[d+2], q3 = sq[d+3];
        a0 = __fmaf_rn(q0, g_Rt[(d+0)*Dn + j], a0);
        a1 = __fmaf_rn(q1, g_Rt[(d+1)*Dn + j], a1);
        a2 = __fmaf_rn(q2, g_Rt[(d+2)*Dn + j], a2);
        a3 = __fmaf_rn(q3, g_Rt[(d+3)*Dn + j], a3);
        b0 = __fmaf_rn(q0, g_St[(d+0)*Dn + j], b0);
        b1 = __fmaf_rn(q1, g_St[(d+1)*Dn + j], b1);
        b2 = __fmaf_rn(q2, g_St[(d+2)*Dn + j], b2);
        b3 = __fmaf_rn(q3, g_St[(d+3)*Dn + j], b3);
    }
    g_qR[(size_t)bq*Dn + j] = (a0 + a1) + (a2 + a3);
    g_qS[(size_t)bq*Dn + j] = (b0 + b1) + (b2 + b3);
}

__device__ __forceinline__ float wsum(float v)
{
#pragma unroll
    for (int o = 16; o > 0; o >>= 1) v += __shfl_xor_sync(0xffffffffu, v, o);
    return v;
}

/* ---- packed f32x2 helpers (two independent IEEE fp32 ops each) ---- */
__device__ __forceinline__ u64 pk2(float lo, float hi)
{ u64 r; asm("mov.b64 %0,{%1,%2};" : "=l"(r) : "f"(lo), "f"(hi)); return r; }
__device__ __forceinline__ u64 dup2(float x)
{ u64 r; asm("mov.b64 %0,{%1,%1};" : "=l"(r) : "f"(x)); return r; }
__device__ __forceinline__ void fma2(u64& acc, u64 a, u64 b)
{ asm("fma.rn.f32x2 %0,%1,%2,%0;" : "+l"(acc) : "l"(a), "l"(b)); }
__device__ __forceinline__ float2 unpk(u64 v)
{ float2 f; asm("mov.b64 {%0,%1},%2;" : "=f"(f.x), "=f"(f.y) : "l"(v)); return f; }

/* ---- main fused kernel: one block = 128 keys of one (b,h), 8 warps,
   16 keys per warp (2 halves of 8 sharing each matrix load) ---- */
__global__ void __launch_bounds__(NTHREADS, 1)
turbo_main(const float* __restrict__ keys, const float* __restrict__ rot,
           const float* __restrict__ levels, float* __restrict__ out)
{
    __shared__ float  sM[Dn*Dn];        /* 64K: Rt -> rot -> St  */
    __shared__ float  sK[TILE*Dn];      /* 64K: keys -> k_hat -> r_hat */
    __shared__ float  sQR[SQn*Dn];      /*  8K */
    __shared__ float  sQS[SQn*Dn];      /*  8K */
    __shared__ float  sTab[256*4];      /*  4K: byte -> 4 level values */
    __shared__ float  sNorm[TILE];
    __shared__ float  sRn[TILE];
    __shared__ unsigned sSign[TILE*4];  /*  2K */
    __shared__ unsigned char sCodeB[TILE*32]; /* 4K: 2-bit yhat codes */

    const int tid = threadIdx.x, w = tid >> 5, lane = tid & 31;
    const int bh  = blockIdx.x >> 5;            /* 32 tiles per bh */
    const int k0  = (blockIdx.x & 31) * TILE;
    const float* keys_blk = keys + ((size_t)bh*SKn + k0)*Dn;

    const float L0 = __ldg(levels+0), L1 = __ldg(levels+1),
                L2 = __ldg(levels+2), L3 = __ldg(levels+3);
    const float bb0 = 0.5f*(L0+L1), bb1 = 0.5f*(L1+L2), bb2 = 0.5f*(L2+L3);

    /* cooperative loads */
    {
        const float4* g = (const float4*)keys_blk;
        float4* s = (float4*)sK;
#pragma unroll
        for (int i = tid; i < TILE*Dn/4; i += NTHREADS) s[i] = g[i];
    }
    {
        const float4* g = (const float4*)g_Rt; float4* s = (float4*)sM;
#pragma unroll
        for (int i = tid; i < Dn*Dn/4; i += NTHREADS) s[i] = g[i];
    }
    {
        const float4* g = (const float4*)(g_qR + bh*SQn*Dn); float4* s = (float4*)sQR;
#pragma unroll
        for (int i = tid; i < SQn*Dn/4; i += NTHREADS) s[i] = g[i];
        g = (const float4*)(g_qS + bh*SQn*Dn); s = (float4*)sQS;
#pragma unroll
        for (int i = tid; i < SQn*Dn/4; i += NTHREADS) s[i] = g[i];
    }
    /* byte -> float4 level decode table (exact level values) */
    {
        unsigned b = tid;
        float v[4];
#pragma unroll
        for (int c = 0; c < 4; ++c) {
            unsigned cc = (b >> (2*c)) & 3u;
            float lo = (cc & 1u) ? L1 : L0;
            float hi = (cc & 1u) ? L3 : L2;
            v[c] = (cc & 2u) ? hi : lo;
        }
        ((float4*)sTab)[b] = make_float4(v[0],v[1],v[2],v[3]);
    }
    __syncthreads();

    const int kb = w*16;

    /* norms + k_hat = fl(k/n), fused warp-local pass (div count unchanged):
       each lane holds its float4 of the row during the reduction, divides it
       once after wsum broadcasts the total, stores back. Own-warp rows only. */
    float nk[16];
#pragma unroll
    for (int i = 0; i < 16; ++i) {
        int key = kb + i;
        float4 v = ((const float4*)(sK + key*Dn))[lane];
        float ss = __fmul_rn(v.x, v.x);
        ss = __fmaf_rn(v.y, v.y, ss);
        ss = __fmaf_rn(v.z, v.z, ss);
        ss = __fmaf_rn(v.w, v.w, ss);
        ss = wsum(ss);
        float n = fmaxf(__fsqrt_rn(ss), 1e-8f);
        nk[i] = n;
        if (lane == 0) sNorm[key] = n;
        float4 h;
        h.x = __fdiv_rn(v.x, n);
        h.y = __fdiv_rn(v.y, n);
        h.z = __fdiv_rn(v.z, n);
        h.w = __fdiv_rn(v.w, n);
        ((float4*)(sK + key*Dn))[lane] = h;
    }
    __syncwarp();

    /* ===== phase 1: y = k_hat @ R^T (seq FMA over d); 2-bit codes ===== */
    {
        u64 axy[16], azw[16];
#pragma unroll
        for (int i = 0; i < 16; ++i) { axy[i] = 0ULL; azw[i] = 0ULL; }
        for (int db = 0; db < Dn; db += 4) {
            u64 rx[4], rz[4];
#pragma unroll
            for (int dd = 0; dd < 4; ++dd) {
                float4 r = ((const float4*)sM)[(db+dd)*32 + lane];
                rx[dd] = pk2(r.x, r.y); rz[dd] = pk2(r.z, r.w);
            }
#pragma unroll
            for (int h = 0; h < 2; ++h) {
                float xs[8][4];
#pragma unroll
                for (int i = 0; i < 8; ++i) {
                    float4 x = *(const float4*)(sK + (kb + h*8 + i)*Dn + db);
                    xs[i][0]=x.x; xs[i][1]=x.y; xs[i][2]=x.z; xs[i][3]=x.w;
                }
#pragma unroll
                for (int dd = 0; dd < 4; ++dd)
#pragma unroll
                    for (int i = 0; i < 8; ++i) {
                        u64 xx = dup2(xs[i][dd]);
                        fma2(axy[h*8+i], xx, rx[dd]);
                        fma2(azw[h*8+i], xx, rz[dd]);
                    }
            }
        }
#pragma unroll
        for (int i = 0; i < 16; ++i) {
            float2 lo = unpk(axy[i]), hi = unpk(azw[i]);
            unsigned c0, c1, c2, c3;
            { float y = lo.x; c0 = (unsigned)(y > bb0) + (unsigned)(y > bb1) + (unsigned)(y > bb2); }
            { float y = lo.y; c1 = (unsigned)(y > bb0) + (unsigned)(y > bb1) + (unsigned)(y > bb2); }
            { float y = hi.x; c2 = (unsigned)(y > bb0) + (unsigned)(y > bb1) + (unsigned)(y > bb2); }
            { float y = hi.y; c3 = (unsigned)(y > bb0) + (unsigned)(y > bb1) + (unsigned)(y > bb2); }
            sCodeB[(kb+i)*32 + lane] = (unsigned char)(c0 | (c1<<2) | (c2<<4) | (c3<<6));
        }
    }
    __syncthreads();

    /* reload matrix slot with R itself (row-major rot[j][d]) */
    {
        const float4* g = (const float4*)rot; float4* s = (float4*)sM;
#pragma unroll
        for (int i = tid; i < Dn*Dn/4; i += NTHREADS) s[i] = g[i];
    }
    __syncthreads();

    /* ===== phase 2: keys_mse = fl(fl(yhat@R)*n); residual; r_hat ===== */
    {
        u64 axy[16], azw[16];
#pragma unroll
        for (int i = 0; i < 16; ++i) { axy[i] = 0ULL; azw[i] = 0ULL; }
        for (int g = 0; g < 32; ++g) {          /* j = 4g..4g+3 */
            u64 rx[4], rz[4];
#pragma unroll
            for (int dd = 0; dd < 4; ++dd) {
                float4 r = ((const float4*)sM)[(4*g+dd)*32 + lane];
                rx[dd] = pk2(r.x, r.y); rz[dd] = pk2(r.z, r.w);
            }
#pragma unroll
            for (int h = 0; h < 2; ++h) {
                float xs[8][4];
#pragma unroll
                for (int i = 0; i < 8; ++i) {
                    float4 x = ((const float4*)sTab)[sCodeB[(kb + h*8 + i)*32 + g]];
                    xs[i][0]=x.x; xs[i][1]=x.y; xs[i][2]=x.z; xs[i][3]=x.w;
                }
#pragma unroll
                for (int dd = 0; dd < 4; ++dd)
#pragma unroll
                    for (int i = 0; i < 8; ++i) {
                        u64 xx = dup2(xs[i][dd]);
                        fma2(axy[h*8+i], xx, rx[dd]);
                        fma2(azw[h*8+i], xx, rz[dd]);
                    }
            }
        }
#pragma unroll
        for (int i = 0; i < 16; ++i) {
            int key = kb + i;
            float n = nk[i];
            float2 lo = unpk(axy[i]), hi = unpk(azw[i]);
            float4 kg = ((const float4*)(keys_blk + (size_t)key*Dn))[lane];
            float4 r;
            r.x = __fadd_rn(kg.x, -__fmul_rn(lo.x, n));
            r.y = __fadd_rn(kg.y, -__fmul_rn(lo.y, n));
            r.z = __fadd_rn(kg.z, -__fmul_rn(hi.x, n));
            r.w = __fadd_rn(kg.w, -__fmul_rn(hi.y, n));
            float ss = __fmul_rn(r.x, r.x);
            ss = __fmaf_rn(r.y, r.y, ss);
            ss = __fmaf_rn(r.z, r.z, ss);
            ss = __fmaf_rn(r.w, r.w, ss);
            ss = wsum(ss);
            float rn = fmaxf(__fsqrt_rn(ss), 1e-10f);
            if (lane == 0) sRn[key] = rn;
            float4 rh;
            rh.x = __fdiv_rn(r.x, rn);
            rh.y = __fdiv_rn(r.y, rn);
            rh.z = __fdiv_rn(r.z, rn);
            rh.w = __fdiv_rn(r.w, rn);
            ((float4*)(sK + key*Dn))[lane] = rh;   /* k_hat -> r_hat */
        }
    }
    __syncthreads();

    /* reload matrix slot: St[d][m] */
    {
        const float4* g = (const float4*)g_St; float4* s = (float4*)sM;
#pragma unroll
        for (int i = tid; i < Dn*Dn/4; i += NTHREADS) s[i] = g[i];
    }
    __syncthreads();

    /* ===== phase 3: proj = r_hat @ S^T (seq FMA over d); signs ===== */
    {
        u64 axy[16], azw[16];
#pragma unroll
        for (int i = 0; i < 16; ++i) { axy[i] = 0ULL; azw[i] = 0ULL; }
        for (int db = 0; db < Dn; db += 4) {
            u64 rx[4], rz[4];
#pragma unroll
            for (int dd = 0; dd < 4; ++dd) {
                float4 r = ((const float4*)sM)[(db+dd)*32 + lane];
                rx[dd] = pk2(r.x, r.y); rz[dd] = pk2(r.z, r.w);
            }
#pragma unroll
            for (int h = 0; h < 2; ++h) {
                float xs[8][4];
#pragma unroll
                for (int i = 0; i < 8; ++i) {
                    float4 x = *(const float4*)(sK + (kb + h*8 + i)*Dn + db);
                    xs[i][0]=x.x; xs[i][1]=x.y; xs[i][2]=x.z; xs[i][3]=x.w;
                }
#pragma unroll
                for (int dd = 0; dd < 4; ++dd)
#pragma unroll
                    for (int i = 0; i < 8; ++i) {
                        u64 xx = dup2(xs[i][dd]);
                        fma2(axy[h*8+i], xx, rx[dd]);
                        fma2(azw[h*8+i], xx, rz[dd]);
                    }
            }
        }
#pragma unroll
        for (int i = 0; i < 16; ++i) {
            float2 lo = unpk(axy[i]), hi = unpk(azw[i]);
            unsigned b0 = __ballot_sync(0xffffffffu, lo.x >= 0.f);
            unsigned b1 = __ballot_sync(0xffffffffu, lo.y >= 0.f);
            unsigned b2 = __ballot_sync(0xffffffffu, hi.x >= 0.f);
            unsigned b3 = __ballot_sync(0xffffffffu, hi.y >= 0.f);
            if (lane == 0) {
                unsigned* sp = sSign + (size_t)(kb+i)*4;
                sp[0]=b0; sp[1]=b1; sp[2]=b2; sp[3]=b3;
            }
        }
    }
    __syncthreads();

    /* ===== epilogue (shfl-free, merged e/s loop): warp -> 2 q rows, lane -> 4 keys ===== */
    {
        const float cq = 0.0097915167f;   /* sqrt(pi/2)/128 */
        const int q0 = 2*w, q1 = 2*w + 1;
        const float* qr0 = sQR + q0*Dn;
        const float* qr1 = sQR + q1*Dn;
        const float* qs0 = sQS + q0*Dn;
        const float* qs1 = sQS + q1*Dn;
        float* og = out + ((size_t)bh*SQn)*SKn + k0;

#pragma unroll
        for (int kc = 0; kc < 4; ++kc) {        /* key columns lane + 32*kc */
            const int key = lane + 32*kc;
            const unsigned char* cK = sCodeB + key*32;
            unsigned w0 = sSign[key*4+0], w1 = sSign[key*4+1],
                     w2 = sSign[key*4+2], w3 = sSign[key*4+3];
            float e0 = 0.f, e1 = 0.f, s0 = 0.f, s1 = 0.f;
#pragma unroll 4
            for (int g = 0; g < 32; ++g) {
                float4 a0 = ((const float4*)qr0)[g];
                float4 a1 = ((const float4*)qr1)[g];
                float4 yv = ((const float4*)sTab)[cK[g]];
                float4 b0 = ((const float4*)qs0)[g];
                float4 b1 = ((const float4*)qs1)[g];
                e0 = __fmaf_rn(a0.x, yv.x, e0); e0 = __fmaf_rn(a0.y, yv.y, e0);
                e0 = __fmaf_rn(a0.z, yv.z, e0); e0 = __fmaf_rn(a0.w, yv.w, e0);
                e1 = __fmaf_rn(a1.x, yv.x, e1); e1 = __fmaf_rn(a1.y, yv.y, e1);
                e1 = __fmaf_rn(a1.z, yv.z, e1); e1 = __fmaf_rn(a1.w, yv.w, e1);
                float f0 = ((w0 >> g) & 1u) ? 1.f : -1.f;
                float f1 = ((w1 >> g) & 1u) ? 1.f : -1.f;
                float f2 = ((w2 >> g) & 1u) ? 1.f : -1.f;
                float f3 = ((w3 >> g) & 1u) ? 1.f : -1.f;
                s0 = __fmaf_rn(f0, b0.x, s0); s0 = __fmaf_rn(f1, b0.y, s0);
                s0 = __fmaf_rn(f2, b0.z, s0); s0 = __fmaf_rn(f3, b0.w, s0);
                s1 = __fmaf_rn(f0, b1.x, s1); s1 = __fmaf_rn(f1, b1.y, s1);
                s1 = __fmaf_rn(f2, b1.z, s1); s1 = __fmaf_rn(f3, b1.w, s1);
            }
            float n = sNorm[key], g2 = cq * sRn[key];
            og[(size_t)q0*SKn + key] = n*e0 + g2*s0;
            og[(size_t)q1*SKn + key] = n*e1 + g2*s1;
        }
    }
}

extern "C" void kernel_launch(void* const* d_in, const int* in_sizes, int n_in,
                              void* d_out, int out_size)
{
    const float* query  = (const float*)d_in[0];
    const float* keys   = (const float*)d_in[1];
    const float* rot    = (const float*)d_in[2];
    const float* S      = (const float*)d_in[3];
    const float* levels = (const float*)d_in[4];
    float* out = (float*)d_out;

    prep1<<<Dn, Dn>>>(rot, S);
    prep_q<<<BHn*SQn, Dn>>>(query);
    turbo_main<<<NBLOCKS, NTHREADS>>>(keys, rot, levels, out);
}